// round 15
// baseline (speedup 1.0000x reference)
#include <cuda_runtime.h>
#include <cuda_fp16.h>
#include <cstdint>
#include <cstddef>

#define B_ 64
#define L_ 512
#define D_ 512
#define F_ 2048
#define E_ 8

__device__ float g_gates[B_ * E_];
__device__ int   g_sched[B_];                      // batches sorted by nact desc
// fragment-permuted fp16 operands (chunk = 16 K-cols: [mg8][lane32] uint4)
__device__ __half g_xh[(size_t)B_ * L_ * D_];      // [b][mt4][ck32]
__device__ __half g_h[(size_t)B_ * E_ * L_ * F_];  // [pair][mt4][ck128]
__device__ __half g_w1h[(size_t)E_ * D_ * F_];     // [e][nt16][ck32]
__device__ __half g_w2h[(size_t)E_ * F_ * D_];     // [e][nt4][ck128]

// 2-stage BK=32: A 2x8KB + B 2x8KB
#define SMEM_BYTES 32768

// ---------------------------------------------------------------------------
__device__ __forceinline__ void mma_f16(float* d, const uint32_t* a, const uint32_t* b) {
    asm volatile(
        "mma.sync.aligned.m16n8k16.row.col.f32.f16.f16.f32 "
        "{%0,%1,%2,%3},{%4,%5,%6,%7},{%8,%9},{%0,%1,%2,%3};\n"
        : "+f"(d[0]), "+f"(d[1]), "+f"(d[2]), "+f"(d[3])
        : "r"(a[0]), "r"(a[1]), "r"(a[2]), "r"(a[3]),
          "r"(b[0]), "r"(b[1]));
}

__device__ __forceinline__ void cp16(uint32_t smem_addr, const void* gsrc) {
    asm volatile("cp.async.cg.shared.global [%0], [%1], 16;" :: "r"(smem_addr), "l"(gsrc));
}
#define CP_COMMIT() asm volatile("cp.async.commit_group;")
#define CP_WAIT1()  asm volatile("cp.async.wait_group 1;")
#define CP_WAIT0()  asm volatile("cp.async.wait_group 0;")

__device__ __forceinline__ float gelu_exact(float v) {
    return 0.5f * v * (1.0f + erff(v * 0.70710678118654752f));
}
__device__ __forceinline__ uint32_t pack2(float a, float b) {
    __half2 h = __floats2half2_rn(a, b);
    return *(uint32_t*)&h;
}

// ---------------------------------------------------------------------------
// prep kernels (unchanged layouts)
// ---------------------------------------------------------------------------
__global__ void permute_x_kernel(const float* __restrict__ x) {
    int kc = blockIdx.x, mt = blockIdx.y, b = blockIdx.z;
    const float* src = x + (size_t)b * L_ * D_;
    uint4* dst = (uint4*)g_xh + (((size_t)b * 4 + mt) * 32 + kc) * 256;
    int tid = threadIdx.x;
    int mg = tid >> 5, lane = tid & 31, g = lane >> 2, c = lane & 3;
    int m = mt * 128 + mg * 16 + g;
    int k = kc * 16 + 2 * c;
    uint4 v;
    v.x = pack2(src[(size_t)m * D_ + k],           src[(size_t)m * D_ + k + 1]);
    v.y = pack2(src[(size_t)(m + 8) * D_ + k],     src[(size_t)(m + 8) * D_ + k + 1]);
    v.z = pack2(src[(size_t)m * D_ + k + 8],       src[(size_t)m * D_ + k + 9]);
    v.w = pack2(src[(size_t)(m + 8) * D_ + k + 8], src[(size_t)(m + 8) * D_ + k + 9]);
    dst[tid] = v;
}

__global__ void permute_w_kernel(const float* __restrict__ src_all,
                                 __half* __restrict__ dst_all, int K, int N) {
    int kt = blockIdx.x, nt = blockIdx.y, e = blockIdx.z;
    int KT = K / 32, NT = N / 128;
    const float* src = src_all + (size_t)e * K * N;
    uint4* dst = (uint4*)dst_all + (((size_t)e * NT + nt) * KT + kt) * 512;
    int tid = threadIdx.x;
    int kc = tid >> 8, np = (tid >> 5) & 7, lane = tid & 31, g = lane >> 2, c = lane & 3;
    int k = kt * 32 + kc * 16 + 2 * c;
    int n0 = nt * 128 + np * 16 + g, n1 = n0 + 8;
    uint4 v;
    v.x = pack2(src[(size_t)k * N + n0],       src[(size_t)(k + 1) * N + n0]);
    v.y = pack2(src[(size_t)(k + 8) * N + n0], src[(size_t)(k + 9) * N + n0]);
    v.z = pack2(src[(size_t)k * N + n1],       src[(size_t)(k + 1) * N + n1]);
    v.w = pack2(src[(size_t)(k + 8) * N + n1], src[(size_t)(k + 9) * N + n1]);
    dst[tid] = v;
}

// ---------------------------------------------------------------------------
// gates + guide loss + longest-first batch schedule for GEMM2
// ---------------------------------------------------------------------------
__global__ void gates_kernel(const float* __restrict__ logits,
                             const int* __restrict__ masks,
                             float* __restrict__ guide_out) {
    __shared__ float s_m[B_];
    __shared__ int s_n[B_];
    int b = threadIdx.x;
    float v[E_];
    float mx = -1e30f;
#pragma unroll
    for (int e = 0; e < E_; ++e) {
        v[e] = logits[b * E_ + e];
        mx = fmaxf(mx, v[e]);
    }
    float s = 0.f;
#pragma unroll
    for (int e = 0; e < E_; ++e) { v[e] = expf(v[e] - mx); s += v[e]; }
    float inv = 1.0f / s;
    float g[E_];
    float msum = 0.f;
    int nact = 0;
#pragma unroll
    for (int e = 0; e < E_; ++e) {
        float raw = v[e] * inv;
        float m = (masks[b * E_ + e] == 1) ? 1.0f : 0.0f;
        g[e] = raw * m;
        msum += g[e];
        nact += (m != 0.0f);
    }
    float inv2 = 1.0f / (msum + 1e-9f);
#pragma unroll
    for (int e = 0; e < E_; ++e) g_gates[b * E_ + e] = g[e] * inv2;
    s_m[b] = msum;
    s_n[b] = nact;
    __syncthreads();
    if (b == 0) {
        float t = 0.f;
        for (int i = 0; i < B_; ++i) t += s_m[i];
        float gl = 1.0f - t / (float)B_;
        guide_out[0] = gl * gl;
        // longest-first: stable sort batches by nact descending
        int pos = 0;
        for (int n = E_; n >= 0; --n)
            for (int i = 0; i < B_; ++i)
                if (s_n[i] == n) g_sched[pos++] = i;
    }
}

// ---------------------------------------------------------------------------
// one BK=32 stage: 2 kc chunks, 4 warps of 64x64, fp16 m16n8k16
// ---------------------------------------------------------------------------
__device__ __forceinline__ void compute_tile(const uint4* A4, const uint4* B4,
                                             int wmg, int wng, int lane,
                                             float acc[4][8][4]) {
#pragma unroll
    for (int kc = 0; kc < 2; ++kc) {
        uint4 af[4], bq[4];
#pragma unroll
        for (int mi = 0; mi < 4; ++mi)
            af[mi] = A4[(kc * 8 + wmg + mi) * 32 + lane];
#pragma unroll
        for (int np = 0; np < 4; ++np)
            bq[np] = B4[(kc * 8 + wng + np) * 32 + lane];
#pragma unroll
        for (int mi = 0; mi < 4; ++mi) {
#pragma unroll
            for (int np = 0; np < 4; ++np) {
                uint32_t b0[2] = { bq[np].x, bq[np].y };
                uint32_t b1[2] = { bq[np].z, bq[np].w };
                mma_f16(acc[mi][2 * np],     (const uint32_t*)&af[mi], b0);
                mma_f16(acc[mi][2 * np + 1], (const uint32_t*)&af[mi], b1);
            }
        }
    }
}

// ---------------------------------------------------------------------------
// GEMM1: h = fp16(gate * gelu(x @ w1 + b1)), DIRECT A-perm register epilogue
// grid (F/128=16, L/128=4, B*E), 128 threads, 2-stage BK=32, 3 CTAs/SM
// ---------------------------------------------------------------------------
__global__ __launch_bounds__(128, 3)
void gemm1_kernel(const float* __restrict__ b1) {
    int pair = blockIdx.z;
    float gate = g_gates[pair];
    if (gate == 0.0f) return;
    int b = pair >> 3;
    int e = pair & 7;
    int mty = blockIdx.y;
    int ntx = blockIdx.x;
    int n0 = ntx * 128;

    extern __shared__ char smraw[];
    uint4* smA = (uint4*)smraw;                 // 2 stages x 512 u4
    uint4* smB = (uint4*)smraw + 1024;          // 2 stages x 512 u4
    uint32_t smb = (uint32_t)__cvta_generic_to_shared(smraw);

    int tid = threadIdx.x;
    int lane = tid & 31;
    int warp = tid >> 5;
    int wmg = (warp >> 1) * 4, wng = (warp & 1) * 4;
    int kcol = lane & 3;

    const uint4* Asrc = (const uint4*)g_xh + (((size_t)b * 4 + mty) * 32) * 256;
    const uint4* Bsrc = (const uint4*)g_w1h + (((size_t)e * 16 + ntx) * 16) * 512;

    float acc[4][8][4];
#pragma unroll
    for (int mi = 0; mi < 4; ++mi)
#pragma unroll
        for (int ni = 0; ni < 8; ++ni)
#pragma unroll
            for (int r = 0; r < 4; ++r) acc[mi][ni][r] = 0.f;

    auto load_stage = [&](int s, int kt) {
        const uint4* Ag = Asrc + (size_t)kt * 512;
        const uint4* Bg = Bsrc + (size_t)kt * 512;
        uint32_t Ab = smb + s * 8192;
        uint32_t Bb = smb + 16384 + s * 8192;
#pragma unroll
        for (int i = 0; i < 4; ++i) {
            cp16(Ab + tid * 16 + i * 2048, Ag + tid + i * 128);
            cp16(Bb + tid * 16 + i * 2048, Bg + tid + i * 128);
        }
        CP_COMMIT();
    };

    const int NK = D_ / 32;   // 16
    load_stage(0, 0);
    int st = 0;
#pragma unroll 2
    for (int kt = 0; kt < NK; ++kt) {
        bool more = (kt + 1 < NK);
        if (more) load_stage(st ^ 1, kt + 1);
        if (more) CP_WAIT1(); else CP_WAIT0();
        __syncthreads();
        compute_tile(smA + st * 512, smB + st * 512, wmg, wng, lane, acc);
        __syncthreads();
        st ^= 1;
    }

    // DIRECT epilogue: accumulator fragments map 1:1 onto A-perm uint4 layout.
    uint4* hbase = (uint4*)g_h + (((size_t)pair * 4 + mty) * 128 + ntx * 8) * 256;
    const float* b1n = b1 + n0;
    int mgbase = (warp >> 1) * 4;
    int kcbase = (warp & 1) * 4;
    int wn = (warp & 1) * 64;
#pragma unroll
    for (int mi = 0; mi < 4; ++mi) {
#pragma unroll
        for (int j = 0; j < 4; ++j) {
            int colL = wn + 16 * j + kcol * 2;
            float bv0 = b1n[colL],     bv1 = b1n[colL + 1];
            float bv8 = b1n[colL + 8], bv9 = b1n[colL + 9];
            const float* a0 = acc[mi][2 * j];
            const float* a1 = acc[mi][2 * j + 1];
            uint4 v;
            v.x = pack2(gate * gelu_exact(a0[0] + bv0), gate * gelu_exact(a0[1] + bv1));
            v.y = pack2(gate * gelu_exact(a0[2] + bv0), gate * gelu_exact(a0[3] + bv1));
            v.z = pack2(gate * gelu_exact(a1[0] + bv8), gate * gelu_exact(a1[1] + bv9));
            v.w = pack2(gate * gelu_exact(a1[2] + bv8), gate * gelu_exact(a1[3] + bv9));
            hbase[(size_t)(kcbase + j) * 256 + (mgbase + mi) * 32 + lane] = v;
        }
    }
}

// ---------------------------------------------------------------------------
// GEMM2: out[b] = sum_e (h[b,e] @ w2[e]) + sum_e g*b2[e]
// grid (D/128=4, L/128=4, B), 128 threads, 2-stage BK=32, 3 CTAs/SM,
// longest-first batch schedule via g_sched
// ---------------------------------------------------------------------------
__global__ __launch_bounds__(128, 3)
void gemm2_kernel(const float* __restrict__ b2,
                  float* __restrict__ out) {
    int b   = g_sched[blockIdx.z];
    int mty = blockIdx.y;
    int ntx = blockIdx.x;
    int m0 = mty * 128, n0 = ntx * 128;
    int tid = threadIdx.x;
    int lane = tid & 31;
    int warp = tid >> 5;
    int wm = (warp >> 1) * 64, wn = (warp & 1) * 64;
    int wmg = (warp >> 1) * 4, wng = (warp & 1) * 4;
    int mrow = lane >> 2, kcol = lane & 3;

    int act[E_]; float gact[E_]; int nact = 0;
#pragma unroll
    for (int e = 0; e < E_; ++e) {
        float g = g_gates[b * E_ + e];
        if (g != 0.0f) { act[nact] = e; gact[nact] = g; ++nact; }
    }
    if (nact == 0) return;   // zero_rows_kernel fills these rows exactly

    extern __shared__ char smraw[];
    uint4* smA = (uint4*)smraw;
    uint4* smB = (uint4*)smraw + 1024;
    uint32_t smb = (uint32_t)__cvta_generic_to_shared(smraw);
    __shared__ float sbias[128];

    {
        float bias = 0.f;
        for (int i = 0; i < nact; ++i)
            bias += gact[i] * b2[act[i] * D_ + n0 + tid];
        sbias[tid] = bias;
    }
    __syncthreads();

    float acc[4][8][4];
#pragma unroll
    for (int mi = 0; mi < 4; ++mi)
#pragma unroll
        for (int ni = 0; ni < 8; ++ni)
#pragma unroll
            for (int r = 0; r < 4; ++r) acc[mi][ni][r] = 0.f;

    const int KPE = F_ / 32;               // 64
    int total = nact * KPE;

    auto load_stage = [&](int s, int t) {
        int ei = t >> 6, kt = t & 63;
        const uint4* Ag = (const uint4*)g_h +
            ((((size_t)(b * E_ + act[ei]) * 4 + mty) * 128) + kt * 2) * 256;
        const uint4* Bg = (const uint4*)g_w2h +
            ((((size_t)act[ei] * 4 + ntx) * 64) + kt) * 512;
        uint32_t Ab = smb + s * 8192;
        uint32_t Bb = smb + 16384 + s * 8192;
#pragma unroll
        for (int i = 0; i < 4; ++i) {
            cp16(Ab + tid * 16 + i * 2048, Ag + tid + i * 128);
            cp16(Bb + tid * 16 + i * 2048, Bg + tid + i * 128);
        }
        CP_COMMIT();
    };

    load_stage(0, 0);
    int st = 0;
#pragma unroll 2
    for (int t = 0; t < total; ++t) {
        bool more = (t + 1 < total);
        if (more) load_stage(st ^ 1, t + 1);
        if (more) CP_WAIT1(); else CP_WAIT0();
        __syncthreads();
        compute_tile(smA + st * 512, smB + st * 512, wmg, wng, lane, acc);
        __syncthreads();
        st ^= 1;
    }

    float* outb = out + (size_t)b * L_ * D_;
#pragma unroll
    for (int mi = 0; mi < 4; ++mi) {
        int r0 = m0 + wm + mi * 16 + mrow;
#pragma unroll
        for (int ni = 0; ni < 8; ++ni) {
            int cl = wn + ni * 8 + kcol * 2;
            int c0 = n0 + cl;
            float bias0 = sbias[cl], bias1 = sbias[cl + 1];
            float2 v0 = make_float2(acc[mi][ni][0] + bias0, acc[mi][ni][1] + bias1);
            float2 v1 = make_float2(acc[mi][ni][2] + bias0, acc[mi][ni][3] + bias1);
            *(float2*)&outb[(size_t)r0 * D_ + c0] = v0;
            *(float2*)&outb[(size_t)(r0 + 8) * D_ + c0] = v1;
        }
    }
}

// zero-fill for batches with all gates zero (exact zeros)
__global__ void zero_rows_kernel(float* __restrict__ out) {
    int b = blockIdx.y;
    bool any = false;
#pragma unroll
    for (int e = 0; e < E_; ++e) any |= (g_gates[b * E_ + e] != 0.0f);
    if (any) return;
    size_t base = (size_t)b * L_ * D_;
    int i = blockIdx.x * blockDim.x + threadIdx.x;
    float4 z = make_float4(0.f, 0.f, 0.f, 0.f);
    for (size_t j = i; j < (size_t)L_ * D_ / 4; j += (size_t)gridDim.x * blockDim.x)
        *((float4*)(out + base) + j) = z;
}

// ---------------------------------------------------------------------------
extern "C" void kernel_launch(void* const* d_in, const int* in_sizes, int n_in,
                              void* d_out, int out_size) {
    const float* x      = (const float*)d_in[0];
    const float* logits = (const float*)d_in[1];
    const int*   masks  = (const int*)d_in[2];
    const float* w1     = (const float*)d_in[3];
    const float* b1     = (const float*)d_in[4];
    const float* w2     = (const float*)d_in[5];
    const float* b2     = (const float*)d_in[6];
    float* out = (float*)d_out;

    static bool attr_done = false;
    if (!attr_done) {
        cudaFuncSetAttribute(gemm1_kernel, cudaFuncAttributeMaxDynamicSharedMemorySize, SMEM_BYTES);
        cudaFuncSetAttribute(gemm2_kernel, cudaFuncAttributeMaxDynamicSharedMemorySize, SMEM_BYTES);
        attr_done = true;
    }

    permute_x_kernel<<<dim3(32, 4, B_), 256>>>(x);
    __half* w1h; cudaGetSymbolAddress((void**)&w1h, g_w1h);
    __half* w2h; cudaGetSymbolAddress((void**)&w2h, g_w2h);
    permute_w_kernel<<<dim3(16, 16, E_), 512>>>(w1, w1h, D_, F_);
    permute_w_kernel<<<dim3(64, 4, E_), 512>>>(w2, w2h, F_, D_);
    gates_kernel<<<1, B_>>>(logits, masks, out + ((size_t)out_size - 1));
    zero_rows_kernel<<<dim3(32, B_), 256>>>(out);

    dim3 g1(16, 4, B_ * E_);
    gemm1_kernel<<<g1, 128, SMEM_BYTES>>>(b1);

    dim3 g2(4, 4, B_);
    gemm2_kernel<<<g2, 128, SMEM_BYTES>>>(b2, out);
}

// round 16
// speedup vs baseline: 1.0771x; 1.0771x over previous
#include <cuda_runtime.h>
#include <cuda_fp16.h>
#include <cstdint>
#include <cstddef>

#define B_ 64
#define L_ 512
#define D_ 512
#define F_ 2048
#define E_ 8

__device__ float g_gates[B_ * E_];
__device__ int   g_sched[B_];                      // batches sorted by nact desc
// fragment-permuted fp16 operands (chunk = 16 K-cols: [mg8][lane32] uint4)
__device__ __half g_xh[(size_t)B_ * L_ * D_];      // [b][mt4][ck32]
__device__ __half g_h[(size_t)B_ * E_ * L_ * F_];  // [pair][mt4][ck128]
__device__ __half g_w1h[(size_t)E_ * D_ * F_];     // [e][nt16][ck32]
__device__ __half g_w2h[(size_t)E_ * F_ * D_];     // [e][nt4][ck128]

// 2-stage BK=32: A 2x8KB + B 2x8KB
#define SMEM_BYTES 32768

// ---------------------------------------------------------------------------
__device__ __forceinline__ void mma_f16(float* d, const uint32_t* a, const uint32_t* b) {
    asm volatile(
        "mma.sync.aligned.m16n8k16.row.col.f32.f16.f16.f32 "
        "{%0,%1,%2,%3},{%4,%5,%6,%7},{%8,%9},{%0,%1,%2,%3};\n"
        : "+f"(d[0]), "+f"(d[1]), "+f"(d[2]), "+f"(d[3])
        : "r"(a[0]), "r"(a[1]), "r"(a[2]), "r"(a[3]),
          "r"(b[0]), "r"(b[1]));
}

__device__ __forceinline__ void cp16(uint32_t smem_addr, const void* gsrc) {
    asm volatile("cp.async.cg.shared.global [%0], [%1], 16;" :: "r"(smem_addr), "l"(gsrc));
}
#define CP_COMMIT() asm volatile("cp.async.commit_group;")
#define CP_WAIT1()  asm volatile("cp.async.wait_group 1;")
#define CP_WAIT0()  asm volatile("cp.async.wait_group 0;")

__device__ __forceinline__ float gelu_exact(float v) {
    return 0.5f * v * (1.0f + erff(v * 0.70710678118654752f));
}
__device__ __forceinline__ uint32_t pack2(float a, float b) {
    __half2 h = __floats2half2_rn(a, b);
    return *(uint32_t*)&h;
}
// streaming (evict-first) 16B / 8B stores
__device__ __forceinline__ void stcs16(uint4* p, uint4 v) {
    asm volatile("st.global.cs.v4.b32 [%0], {%1,%2,%3,%4};"
                 :: "l"(p), "r"(v.x), "r"(v.y), "r"(v.z), "r"(v.w) : "memory");
}
__device__ __forceinline__ void stcs8(float2* p, float2 v) {
    asm volatile("st.global.cs.v2.f32 [%0], {%1,%2};"
                 :: "l"(p), "f"(v.x), "f"(v.y) : "memory");
}

// ---------------------------------------------------------------------------
// prep kernels (unchanged layouts)
// ---------------------------------------------------------------------------
__global__ void permute_x_kernel(const float* __restrict__ x) {
    int kc = blockIdx.x, mt = blockIdx.y, b = blockIdx.z;
    const float* src = x + (size_t)b * L_ * D_;
    uint4* dst = (uint4*)g_xh + (((size_t)b * 4 + mt) * 32 + kc) * 256;
    int tid = threadIdx.x;
    int mg = tid >> 5, lane = tid & 31, g = lane >> 2, c = lane & 3;
    int m = mt * 128 + mg * 16 + g;
    int k = kc * 16 + 2 * c;
    uint4 v;
    v.x = pack2(src[(size_t)m * D_ + k],           src[(size_t)m * D_ + k + 1]);
    v.y = pack2(src[(size_t)(m + 8) * D_ + k],     src[(size_t)(m + 8) * D_ + k + 1]);
    v.z = pack2(src[(size_t)m * D_ + k + 8],       src[(size_t)m * D_ + k + 9]);
    v.w = pack2(src[(size_t)(m + 8) * D_ + k + 8], src[(size_t)(m + 8) * D_ + k + 9]);
    dst[tid] = v;
}

__global__ void permute_w_kernel(const float* __restrict__ src_all,
                                 __half* __restrict__ dst_all, int K, int N) {
    int kt = blockIdx.x, nt = blockIdx.y, e = blockIdx.z;
    int KT = K / 32, NT = N / 128;
    const float* src = src_all + (size_t)e * K * N;
    uint4* dst = (uint4*)dst_all + (((size_t)e * NT + nt) * KT + kt) * 512;
    int tid = threadIdx.x;
    int kc = tid >> 8, np = (tid >> 5) & 7, lane = tid & 31, g = lane >> 2, c = lane & 3;
    int k = kt * 32 + kc * 16 + 2 * c;
    int n0 = nt * 128 + np * 16 + g, n1 = n0 + 8;
    uint4 v;
    v.x = pack2(src[(size_t)k * N + n0],       src[(size_t)(k + 1) * N + n0]);
    v.y = pack2(src[(size_t)(k + 8) * N + n0], src[(size_t)(k + 9) * N + n0]);
    v.z = pack2(src[(size_t)k * N + n1],       src[(size_t)(k + 1) * N + n1]);
    v.w = pack2(src[(size_t)(k + 8) * N + n1], src[(size_t)(k + 9) * N + n1]);
    dst[tid] = v;
}

// ---------------------------------------------------------------------------
// gates + guide loss + longest-first batch schedule for GEMM2
// ---------------------------------------------------------------------------
__global__ void gates_kernel(const float* __restrict__ logits,
                             const int* __restrict__ masks,
                             float* __restrict__ guide_out) {
    __shared__ float s_m[B_];
    __shared__ int s_n[B_];
    int b = threadIdx.x;
    float v[E_];
    float mx = -1e30f;
#pragma unroll
    for (int e = 0; e < E_; ++e) {
        v[e] = logits[b * E_ + e];
        mx = fmaxf(mx, v[e]);
    }
    float s = 0.f;
#pragma unroll
    for (int e = 0; e < E_; ++e) { v[e] = expf(v[e] - mx); s += v[e]; }
    float inv = 1.0f / s;
    float g[E_];
    float msum = 0.f;
    int nact = 0;
#pragma unroll
    for (int e = 0; e < E_; ++e) {
        float raw = v[e] * inv;
        float m = (masks[b * E_ + e] == 1) ? 1.0f : 0.0f;
        g[e] = raw * m;
        msum += g[e];
        nact += (m != 0.0f);
    }
    float inv2 = 1.0f / (msum + 1e-9f);
#pragma unroll
    for (int e = 0; e < E_; ++e) g_gates[b * E_ + e] = g[e] * inv2;
    s_m[b] = msum;
    s_n[b] = nact;
    __syncthreads();
    if (b == 0) {
        float t = 0.f;
        for (int i = 0; i < B_; ++i) t += s_m[i];
        float gl = 1.0f - t / (float)B_;
        guide_out[0] = gl * gl;
        // longest-first: stable sort batches by nact descending
        int pos = 0;
        for (int n = E_; n >= 0; --n)
            for (int i = 0; i < B_; ++i)
                if (s_n[i] == n) g_sched[pos++] = i;
    }
}

// ---------------------------------------------------------------------------
// one BK=32 stage: 2 kc chunks, 4 warps of 64x64, fp16 m16n8k16
// ---------------------------------------------------------------------------
__device__ __forceinline__ void compute_tile(const uint4* A4, const uint4* B4,
                                             int wmg, int wng, int lane,
                                             float acc[4][8][4]) {
#pragma unroll
    for (int kc = 0; kc < 2; ++kc) {
        uint4 af[4], bq[4];
#pragma unroll
        for (int mi = 0; mi < 4; ++mi)
            af[mi] = A4[(kc * 8 + wmg + mi) * 32 + lane];
#pragma unroll
        for (int np = 0; np < 4; ++np)
            bq[np] = B4[(kc * 8 + wng + np) * 32 + lane];
#pragma unroll
        for (int mi = 0; mi < 4; ++mi) {
#pragma unroll
            for (int np = 0; np < 4; ++np) {
                uint32_t b0[2] = { bq[np].x, bq[np].y };
                uint32_t b1[2] = { bq[np].z, bq[np].w };
                mma_f16(acc[mi][2 * np],     (const uint32_t*)&af[mi], b0);
                mma_f16(acc[mi][2 * np + 1], (const uint32_t*)&af[mi], b1);
            }
        }
    }
}

// ---------------------------------------------------------------------------
// GEMM1: h = fp16(gate * gelu(x @ w1 + b1)), DIRECT A-perm register epilogue
// grid (F/128=16, L/128=4, B*E), 128 threads, 2-stage BK=32
// ---------------------------------------------------------------------------
__global__ __launch_bounds__(128, 2)
void gemm1_kernel(const float* __restrict__ b1) {
    int pair = blockIdx.z;
    float gate = g_gates[pair];
    if (gate == 0.0f) return;
    int b = pair >> 3;
    int e = pair & 7;
    int mty = blockIdx.y;
    int ntx = blockIdx.x;
    int n0 = ntx * 128;

    extern __shared__ char smraw[];
    uint4* smA = (uint4*)smraw;                 // 2 stages x 512 u4
    uint4* smB = (uint4*)smraw + 1024;          // 2 stages x 512 u4
    uint32_t smb = (uint32_t)__cvta_generic_to_shared(smraw);

    int tid = threadIdx.x;
    int lane = tid & 31;
    int warp = tid >> 5;
    int wmg = (warp >> 1) * 4, wng = (warp & 1) * 4;
    int kcol = lane & 3;

    const uint4* Asrc = (const uint4*)g_xh + (((size_t)b * 4 + mty) * 32) * 256;
    const uint4* Bsrc = (const uint4*)g_w1h + (((size_t)e * 16 + ntx) * 16) * 512;

    float acc[4][8][4];
#pragma unroll
    for (int mi = 0; mi < 4; ++mi)
#pragma unroll
        for (int ni = 0; ni < 8; ++ni)
#pragma unroll
            for (int r = 0; r < 4; ++r) acc[mi][ni][r] = 0.f;

    auto load_stage = [&](int s, int kt) {
        const uint4* Ag = Asrc + (size_t)kt * 512;
        const uint4* Bg = Bsrc + (size_t)kt * 512;
        uint32_t Ab = smb + s * 8192;
        uint32_t Bb = smb + 16384 + s * 8192;
#pragma unroll
        for (int i = 0; i < 4; ++i) {
            cp16(Ab + tid * 16 + i * 2048, Ag + tid + i * 128);
            cp16(Bb + tid * 16 + i * 2048, Bg + tid + i * 128);
        }
        CP_COMMIT();
    };

    const int NK = D_ / 32;   // 16
    load_stage(0, 0);
    int st = 0;
    for (int kt = 0; kt < NK; ++kt) {
        bool more = (kt + 1 < NK);
        if (more) load_stage(st ^ 1, kt + 1);
        if (more) CP_WAIT1(); else CP_WAIT0();
        __syncthreads();
        compute_tile(smA + st * 512, smB + st * 512, wmg, wng, lane, acc);
        __syncthreads();
        st ^= 1;
    }

    // DIRECT epilogue: accumulator fragments map 1:1 onto A-perm uint4 layout.
    // Streaming stores (.cs) — h is far larger than L2 and not re-read within
    // this kernel; keep w1h/xh resident instead.
    uint4* hbase = (uint4*)g_h + (((size_t)pair * 4 + mty) * 128 + ntx * 8) * 256;
    const float* b1n = b1 + n0;
    int mgbase = (warp >> 1) * 4;
    int kcbase = (warp & 1) * 4;
    int wn = (warp & 1) * 64;
#pragma unroll
    for (int mi = 0; mi < 4; ++mi) {
#pragma unroll
        for (int j = 0; j < 4; ++j) {
            int colL = wn + 16 * j + kcol * 2;
            float bv0 = b1n[colL],     bv1 = b1n[colL + 1];
            float bv8 = b1n[colL + 8], bv9 = b1n[colL + 9];
            const float* a0 = acc[mi][2 * j];
            const float* a1 = acc[mi][2 * j + 1];
            uint4 v;
            v.x = pack2(gate * gelu_exact(a0[0] + bv0), gate * gelu_exact(a0[1] + bv1));
            v.y = pack2(gate * gelu_exact(a0[2] + bv0), gate * gelu_exact(a0[3] + bv1));
            v.z = pack2(gate * gelu_exact(a1[0] + bv8), gate * gelu_exact(a1[1] + bv9));
            v.w = pack2(gate * gelu_exact(a1[2] + bv8), gate * gelu_exact(a1[3] + bv9));
            stcs16(&hbase[(size_t)(kcbase + j) * 256 + (mgbase + mi) * 32 + lane], v);
        }
    }
}

// ---------------------------------------------------------------------------
// GEMM2: out[b] = sum_e (h[b,e] @ w2[e]) + sum_e g*b2[e]
// grid (D/128=4, L/128=4, B), 128 threads, 2-stage BK=32,
// longest-first batch schedule via g_sched; streaming out stores
// ---------------------------------------------------------------------------
__global__ __launch_bounds__(128, 2)
void gemm2_kernel(const float* __restrict__ b2,
                  float* __restrict__ out) {
    int b   = g_sched[blockIdx.z];
    int mty = blockIdx.y;
    int ntx = blockIdx.x;
    int m0 = mty * 128, n0 = ntx * 128;
    int tid = threadIdx.x;
    int lane = tid & 31;
    int warp = tid >> 5;
    int wm = (warp >> 1) * 64, wn = (warp & 1) * 64;
    int wmg = (warp >> 1) * 4, wng = (warp & 1) * 4;
    int mrow = lane >> 2, kcol = lane & 3;

    int act[E_]; float gact[E_]; int nact = 0;
#pragma unroll
    for (int e = 0; e < E_; ++e) {
        float g = g_gates[b * E_ + e];
        if (g != 0.0f) { act[nact] = e; gact[nact] = g; ++nact; }
    }
    if (nact == 0) return;   // zero_rows_kernel fills these rows exactly

    extern __shared__ char smraw[];
    uint4* smA = (uint4*)smraw;
    uint4* smB = (uint4*)smraw + 1024;
    uint32_t smb = (uint32_t)__cvta_generic_to_shared(smraw);
    __shared__ float sbias[128];

    {
        float bias = 0.f;
        for (int i = 0; i < nact; ++i)
            bias += gact[i] * b2[act[i] * D_ + n0 + tid];
        sbias[tid] = bias;
    }
    __syncthreads();

    float acc[4][8][4];
#pragma unroll
    for (int mi = 0; mi < 4; ++mi)
#pragma unroll
        for (int ni = 0; ni < 8; ++ni)
#pragma unroll
            for (int r = 0; r < 4; ++r) acc[mi][ni][r] = 0.f;

    const int KPE = F_ / 32;               // 64
    int total = nact * KPE;

    auto load_stage = [&](int s, int t) {
        int ei = t >> 6, kt = t & 63;
        const uint4* Ag = (const uint4*)g_h +
            ((((size_t)(b * E_ + act[ei]) * 4 + mty) * 128) + kt * 2) * 256;
        const uint4* Bg = (const uint4*)g_w2h +
            ((((size_t)act[ei] * 4 + ntx) * 64) + kt) * 512;
        uint32_t Ab = smb + s * 8192;
        uint32_t Bb = smb + 16384 + s * 8192;
#pragma unroll
        for (int i = 0; i < 4; ++i) {
            cp16(Ab + tid * 16 + i * 2048, Ag + tid + i * 128);
            cp16(Bb + tid * 16 + i * 2048, Bg + tid + i * 128);
        }
        CP_COMMIT();
    };

    load_stage(0, 0);
    int st = 0;
    for (int t = 0; t < total; ++t) {
        bool more = (t + 1 < total);
        if (more) load_stage(st ^ 1, t + 1);
        if (more) CP_WAIT1(); else CP_WAIT0();
        __syncthreads();
        compute_tile(smA + st * 512, smB + st * 512, wmg, wng, lane, acc);
        __syncthreads();
        st ^= 1;
    }

    float* outb = out + (size_t)b * L_ * D_;
#pragma unroll
    for (int mi = 0; mi < 4; ++mi) {
        int r0 = m0 + wm + mi * 16 + mrow;
#pragma unroll
        for (int ni = 0; ni < 8; ++ni) {
            int cl = wn + ni * 8 + kcol * 2;
            int c0 = n0 + cl;
            float bias0 = sbias[cl], bias1 = sbias[cl + 1];
            float2 v0 = make_float2(acc[mi][ni][0] + bias0, acc[mi][ni][1] + bias1);
            float2 v1 = make_float2(acc[mi][ni][2] + bias0, acc[mi][ni][3] + bias1);
            stcs8((float2*)&outb[(size_t)r0 * D_ + c0], v0);
            stcs8((float2*)&outb[(size_t)(r0 + 8) * D_ + c0], v1);
        }
    }
}

// zero-fill for batches with all gates zero (exact zeros)
__global__ void zero_rows_kernel(float* __restrict__ out) {
    int b = blockIdx.y;
    bool any = false;
#pragma unroll
    for (int e = 0; e < E_; ++e) any |= (g_gates[b * E_ + e] != 0.0f);
    if (any) return;
    size_t base = (size_t)b * L_ * D_;
    int i = blockIdx.x * blockDim.x + threadIdx.x;
    float4 z = make_float4(0.f, 0.f, 0.f, 0.f);
    for (size_t j = i; j < (size_t)L_ * D_ / 4; j += (size_t)gridDim.x * blockDim.x)
        *((float4*)(out + base) + j) = z;
}

// ---------------------------------------------------------------------------
extern "C" void kernel_launch(void* const* d_in, const int* in_sizes, int n_in,
                              void* d_out, int out_size) {
    const float* x      = (const float*)d_in[0];
    const float* logits = (const float*)d_in[1];
    const int*   masks  = (const int*)d_in[2];
    const float* w1     = (const float*)d_in[3];
    const float* b1     = (const float*)d_in[4];
    const float* w2     = (const float*)d_in[5];
    const float* b2     = (const float*)d_in[6];
    float* out = (float*)d_out;

    static bool attr_done = false;
    if (!attr_done) {
        cudaFuncSetAttribute(gemm1_kernel, cudaFuncAttributeMaxDynamicSharedMemorySize, SMEM_BYTES);
        cudaFuncSetAttribute(gemm2_kernel, cudaFuncAttributeMaxDynamicSharedMemorySize, SMEM_BYTES);
        attr_done = true;
    }

    permute_x_kernel<<<dim3(32, 4, B_), 256>>>(x);
    __half* w1h; cudaGetSymbolAddress((void**)&w1h, g_w1h);
    __half* w2h; cudaGetSymbolAddress((void**)&w2h, g_w2h);
    permute_w_kernel<<<dim3(16, 16, E_), 512>>>(w1, w1h, D_, F_);
    permute_w_kernel<<<dim3(64, 4, E_), 512>>>(w2, w2h, F_, D_);
    gates_kernel<<<1, B_>>>(logits, masks, out + ((size_t)out_size - 1));
    zero_rows_kernel<<<dim3(32, B_), 256>>>(out);

    dim3 g1(16, 4, B_ * E_);
    gemm1_kernel<<<g1, 128, SMEM_BYTES>>>(b1);

    dim3 g2(4, 4, B_);
    gemm2_kernel<<<g2, 128, SMEM_BYTES>>>(b2, out);
}